// round 1
// baseline (speedup 1.0000x reference)
#include <cuda_runtime.h>
#include <cuda_bf16.h>

// Chamfer distance for B=2, N=M=8192, C=3 fp32 point clouds.
// dir 0: queries = pos   (N), targets = x_hat (M)
// dir 1: queries = x_hat (M), targets = pos   (N)
// rec_loss = sum(min d^2, dir0)/(B*N) + sum(min d^2, dir1)/(B*M); loss = rec_loss.

#define BLOCK 256
#define TILE  512
#define MAX_PARTIALS 8192

__device__ float g_partials[MAX_PARTIALS];

__global__ void chamfer_min_kernel(const float* __restrict__ pos,
                                   const float* __restrict__ xhat,
                                   int N, int M, int B) {
    const int dir = blockIdx.z;       // 0 or 1
    const int b   = blockIdx.y;       // batch
    const int nQ  = (dir == 0) ? N : M;
    const int nT  = (dir == 0) ? M : N;
    const float* __restrict__ Q = (dir == 0) ? pos  : xhat;
    const float* __restrict__ T = (dir == 0) ? xhat : pos;

    const int q = blockIdx.x * BLOCK + threadIdx.x;
    const bool valid = (q < nQ);

    __shared__ float4 tile[TILE];
    __shared__ float  red[BLOCK / 32];

    // Per-query precompute: d(q,t) = qn + (tn - 2 q.t)
    float m2x = 0.f, m2y = 0.f, m2z = 0.f, qn = 0.f;
    if (valid) {
        const float* qp = Q + ((size_t)b * nQ + q) * 3;
        float qx = qp[0], qy = qp[1], qz = qp[2];
        m2x = -2.0f * qx;
        m2y = -2.0f * qy;
        m2z = -2.0f * qz;
        qn  = qx * qx + qy * qy + qz * qz;
    }

    float best = 3.4e38f;
    const float* __restrict__ Tb = T + (size_t)b * nT * 3;

    for (int t0 = 0; t0 < nT; t0 += TILE) {
        const int cnt = min(TILE, nT - t0);
        // Cooperative load of target tile: pack xyz + squared norm into float4.
        for (int i = threadIdx.x; i < cnt; i += BLOCK) {
            const float* tp = Tb + (size_t)(t0 + i) * 3;
            float tx = tp[0], ty = tp[1], tz = tp[2];
            tile[i] = make_float4(tx, ty, tz,
                                  tx * tx + ty * ty + tz * tz);
        }
        __syncthreads();

        if (cnt == TILE) {
#pragma unroll 8
            for (int j = 0; j < TILE; ++j) {
                float4 t = tile[j];
                float d = fmaf(m2x, t.x, fmaf(m2y, t.y, fmaf(m2z, t.z, t.w)));
                best = fminf(best, d);
            }
        } else {
            for (int j = 0; j < cnt; ++j) {
                float4 t = tile[j];
                float d = fmaf(m2x, t.x, fmaf(m2y, t.y, fmaf(m2z, t.z, t.w)));
                best = fminf(best, d);
            }
        }
        __syncthreads();
    }

    float dist = valid ? fmaxf(qn + best, 0.0f) : 0.0f;

    // Deterministic block-level sum (no atomics).
#pragma unroll
    for (int o = 16; o > 0; o >>= 1)
        dist += __shfl_xor_sync(0xffffffffu, dist, o);
    if ((threadIdx.x & 31) == 0) red[threadIdx.x >> 5] = dist;
    __syncthreads();
    if (threadIdx.x == 0) {
        float s = 0.f;
#pragma unroll
        for (int w = 0; w < BLOCK / 32; ++w) s += red[w];
        g_partials[((size_t)dir * gridDim.y + b) * gridDim.x + blockIdx.x] = s;
    }
}

__global__ void chamfer_finalize_kernel(float* __restrict__ out, int out_size,
                                        int N, int M, int B, int nbx) {
    // Single block. Deterministic tree reduction over partials.
    const int per_dir = B * nbx;   // partials per direction
    float s0 = 0.f, s1 = 0.f;
    for (int i = threadIdx.x; i < per_dir; i += blockDim.x) {
        s0 += g_partials[i];
        s1 += g_partials[per_dir + i];
    }
#pragma unroll
    for (int o = 16; o > 0; o >>= 1) {
        s0 += __shfl_xor_sync(0xffffffffu, s0, o);
        s1 += __shfl_xor_sync(0xffffffffu, s1, o);
    }
    __shared__ float r0[8], r1[8];
    const int nw = (blockDim.x + 31) / 32;
    if ((threadIdx.x & 31) == 0) {
        r0[threadIdx.x >> 5] = s0;
        r1[threadIdx.x >> 5] = s1;
    }
    __syncthreads();
    if (threadIdx.x == 0) {
        float t0 = 0.f, t1 = 0.f;
        for (int w = 0; w < nw; ++w) { t0 += r0[w]; t1 += r1[w]; }
        float rec = t0 / (float)((size_t)B * N) + t1 / (float)((size_t)B * M);
        // output: (loss, rec_loss), loss = 1.0 * rec_loss
        for (int i = 0; i < out_size; ++i) out[i] = rec;
    }
}

extern "C" void kernel_launch(void* const* d_in, const int* in_sizes, int n_in,
                              void* d_out, int out_size) {
    const float* pos  = (const float*)d_in[0];
    const float* xhat = (const float*)d_in[1];

    const int B = 2;  // per reference: pos [2, 8192, 3], x_hat [2, 8192, 3]
    const int N = in_sizes[0] / (B * 3);
    const int M = in_sizes[1] / (B * 3);

    const int maxQ = (N > M) ? N : M;
    const int nbx  = (maxQ + BLOCK - 1) / BLOCK;

    dim3 grid(nbx, B, 2);
    chamfer_min_kernel<<<grid, BLOCK>>>(pos, xhat, N, M, B);
    chamfer_finalize_kernel<<<1, 256>>>((float*)d_out, out_size, N, M, B, nbx);
}

// round 2
// speedup vs baseline: 1.7432x; 1.7432x over previous
#include <cuda_runtime.h>
#include <cuda_bf16.h>

// Chamfer distance, B=2, N=M=8192, C=3 fp32.
// d(q,t) = ||q||^2 + (||t||^2 - 2 q.t); min over t, mean over q, both directions.
// Kernel 1: per (dir, batch, query-block, target-segment) compute per-query min of
//           (||t||^2 - 2 q.t) over the segment using packed f32x2 FMAs.
// Kernel 2: reduce mins across segments, add ||q||^2, block-sum.
// Kernel 3: finalize scalar.

#define BLOCK   256
#define QPT     4            // queries per thread
#define SEG_MAX 512          // targets per segment (tile fits smem: 512*16B = 8KB)
#define S_MAX   32
#define B_MAX   4
#define NQ_MAX  8192

// [dir][b][s][q]  (coalesced writes in k1, coalesced reads in k2)
__device__ float g_qmin[2 * B_MAX * S_MAX * NQ_MAX];
__device__ float g_partials[2 * B_MAX * 64];

#define FMA2(d, a, b, c) \
    asm("fma.rn.f32x2 %0, %1, %2, %3;" : "=l"(d) : "l"(a), "l"(b), "l"(c))
#define PACK2(d, lo, hi) \
    asm("mov.b64 %0, {%1, %2};" : "=l"(d) : "f"(lo), "f"(hi))
#define UNPACK2(lo, hi, d) \
    asm("mov.b64 {%0, %1}, %2;" : "=f"(lo), "=f"(hi) : "l"(d))

__global__ __launch_bounds__(BLOCK)
void chamfer_seg_kernel(const float* __restrict__ pos,
                        const float* __restrict__ xhat,
                        int N, int M, int B, int S, int segSize) {
    const int yb  = blockIdx.y;          // dir*B + b
    const int dir = yb / B;
    const int b   = yb % B;
    const int s   = blockIdx.z;

    const int nQ = (dir == 0) ? N : M;
    const int nT = (dir == 0) ? M : N;
    const float* __restrict__ Q = (dir == 0) ? pos  : xhat;
    const float* __restrict__ T = (dir == 0) ? xhat : pos;

    // ---- load target segment into smem, SoA-pair packed layout ----
    // pair p: tile[2p] = {pack(x0,x1), pack(y0,y1)}, tile[2p+1] = {pack(z0,z1), pack(w0,w1)}
    __shared__ ulonglong2 tile[SEG_MAX];   // SEG_MAX/2 pairs * 2 entries

    const int t0  = s * segSize;
    const int cnt = min(segSize, nT - t0);
    if (cnt <= 0) return;
    const int nPairs = (cnt + 1) >> 1;

    const float* __restrict__ Tb = T + (size_t)b * nT * 3;
    for (int p = threadIdx.x; p < nPairs; p += BLOCK) {
        const int i0 = t0 + 2 * p;
        const float* tp0 = Tb + (size_t)i0 * 3;
        float x0 = tp0[0], y0 = tp0[1], z0 = tp0[2];
        float w0 = x0 * x0 + y0 * y0 + z0 * z0;
        float x1 = 0.f, y1 = 0.f, z1 = 0.f, w1 = 1e30f;
        if (2 * p + 1 < cnt) {
            const float* tp1 = tp0 + 3;
            x1 = tp1[0]; y1 = tp1[1]; z1 = tp1[2];
            w1 = x1 * x1 + y1 * y1 + z1 * z1;
        }
        ulonglong2 a, c;
        PACK2(a.x, x0, x1);
        PACK2(a.y, y0, y1);
        PACK2(c.x, z0, z1);
        PACK2(c.y, w0, w1);
        tile[2 * p]     = a;
        tile[2 * p + 1] = c;
    }
    __syncthreads();

    // ---- per-thread queries ----
    const int qBase = blockIdx.x * (BLOCK * QPT) + threadIdx.x;
    unsigned long long m2x2[QPT], m2y2[QPT], m2z2[QPT];
    float bestA[QPT], bestB[QPT];
    bool qvalid[QPT];

#pragma unroll
    for (int k = 0; k < QPT; ++k) {
        const int q = qBase + k * BLOCK;
        qvalid[k] = (q < nQ);
        float qx = 0.f, qy = 0.f, qz = 0.f;
        if (qvalid[k]) {
            const float* qp = Q + ((size_t)b * nQ + q) * 3;
            qx = qp[0]; qy = qp[1]; qz = qp[2];
        }
        const float mx = -2.0f * qx, my = -2.0f * qy, mz = -2.0f * qz;
        PACK2(m2x2[k], mx, mx);
        PACK2(m2y2[k], my, my);
        PACK2(m2z2[k], mz, mz);
        bestA[k] = 3.4e38f;
        bestB[k] = 3.4e38f;
    }

    // ---- main loop over target pairs ----
    const ulonglong2* __restrict__ tp = tile;
#pragma unroll 4
    for (int j = 0; j < nPairs; ++j) {
        const ulonglong2 a = tp[2 * j];       // x2, y2
        const ulonglong2 c = tp[2 * j + 1];   // z2, w2
#pragma unroll
        for (int k = 0; k < QPT; ++k) {
            unsigned long long d;
            FMA2(d, m2z2[k], c.x, c.y);       // z*mz + w
            FMA2(d, m2y2[k], a.y, d);         // + y*my
            FMA2(d, m2x2[k], a.x, d);         // + x*mx
            float dlo, dhi;
            UNPACK2(dlo, dhi, d);
            bestA[k] = fminf(bestA[k], dlo);
            bestB[k] = fminf(bestB[k], dhi);
        }
    }

    // ---- write per-query segment min ----
    float* __restrict__ outp = g_qmin + ((size_t)(yb) * S + s) * nQ;
#pragma unroll
    for (int k = 0; k < QPT; ++k) {
        if (qvalid[k]) {
            const int q = qBase + k * BLOCK;
            outp[q] = fminf(bestA[k], bestB[k]);
        }
    }
}

__global__ void chamfer_reduce_kernel(const float* __restrict__ pos,
                                      const float* __restrict__ xhat,
                                      int N, int M, int B, int S) {
    const int yb  = blockIdx.y;          // dir*B + b
    const int dir = yb / B;
    const int b   = yb % B;
    const int nQ  = (dir == 0) ? N : M;
    const float* __restrict__ Q = (dir == 0) ? pos : xhat;

    const int q = blockIdx.x * blockDim.x + threadIdx.x;
    float dist = 0.f;
    if (q < nQ) {
        const float* __restrict__ mp = g_qmin + (size_t)yb * S * nQ + q;
        float mv = mp[0];
        for (int s = 1; s < S; ++s) mv = fminf(mv, mp[(size_t)s * nQ]);
        const float* qp = Q + ((size_t)b * nQ + q) * 3;
        const float qn = qp[0] * qp[0] + qp[1] * qp[1] + qp[2] * qp[2];
        dist = fmaxf(qn + mv, 0.0f);
    }

    // deterministic block sum
    __shared__ float red[8];
#pragma unroll
    for (int o = 16; o > 0; o >>= 1)
        dist += __shfl_xor_sync(0xffffffffu, dist, o);
    if ((threadIdx.x & 31) == 0) red[threadIdx.x >> 5] = dist;
    __syncthreads();
    if (threadIdx.x == 0) {
        float sum = 0.f;
        const int nw = blockDim.x >> 5;
        for (int w = 0; w < nw; ++w) sum += red[w];
        g_partials[(size_t)yb * gridDim.x + blockIdx.x] = sum;
    }
}

__global__ void chamfer_finalize_kernel(float* __restrict__ out, int out_size,
                                        int N, int M, int B, int nbx) {
    float s0 = 0.f, s1 = 0.f;   // dir0 (queries=pos, count B*N), dir1 (B*M)
    const int per_dir = B * nbx;
    for (int i = threadIdx.x; i < per_dir; i += blockDim.x) {
        s0 += g_partials[i];
        s1 += g_partials[per_dir + i];
    }
#pragma unroll
    for (int o = 16; o > 0; o >>= 1) {
        s0 += __shfl_xor_sync(0xffffffffu, s0, o);
        s1 += __shfl_xor_sync(0xffffffffu, s1, o);
    }
    __shared__ float r0[8], r1[8];
    const int nw = (blockDim.x + 31) >> 5;
    if ((threadIdx.x & 31) == 0) {
        r0[threadIdx.x >> 5] = s0;
        r1[threadIdx.x >> 5] = s1;
    }
    __syncthreads();
    if (threadIdx.x == 0) {
        float t0 = 0.f, t1 = 0.f;
        for (int w = 0; w < nw; ++w) { t0 += r0[w]; t1 += r1[w]; }
        float rec = t0 / (float)((size_t)B * N) + t1 / (float)((size_t)B * M);
        for (int i = 0; i < out_size; ++i) out[i] = rec;
    }
}

extern "C" void kernel_launch(void* const* d_in, const int* in_sizes, int n_in,
                              void* d_out, int out_size) {
    const float* pos  = (const float*)d_in[0];
    const float* xhat = (const float*)d_in[1];

    const int B = 2;
    const int N = in_sizes[0] / (B * 3);
    const int M = in_sizes[1] / (B * 3);

    const int maxT = (N > M) ? N : M;
    int S = (maxT + SEG_MAX - 1) / SEG_MAX;      // segments of <= SEG_MAX targets
    if (S > S_MAX) S = S_MAX;
    const int segSize = (maxT + S - 1) / S;

    const int maxQ = (N > M) ? N : M;
    const int nbx1 = (maxQ + BLOCK * QPT - 1) / (BLOCK * QPT);

    dim3 g1(nbx1, 2 * B, S);
    chamfer_seg_kernel<<<g1, BLOCK>>>(pos, xhat, N, M, B, S, segSize);

    const int nbx2 = (maxQ + BLOCK - 1) / BLOCK;
    dim3 g2(nbx2, 2 * B, 1);
    chamfer_reduce_kernel<<<g2, BLOCK>>>(pos, xhat, N, M, B, S);

    chamfer_finalize_kernel<<<1, 256>>>((float*)d_out, out_size, N, M, B, nbx2);
}